// round 15
// baseline (speedup 1.0000x reference)
#include <cuda_runtime.h>
#include <stdint.h>

#define DN    2048
#define NWORDS  64      // 2048 bits / 32
#define KMAX    32
#define RCAP   160      // reverse-adjacency capacity (in-degree ~Poisson(31), max ~60)
#define NT     128      // k_main block size: 16 CTA/SM -> all 2048 CTAs resident
#define SENT  0xBF800000u   // bit pattern of -1.0f; legit values are in [0,1]

// ---------------- device scratch (no allocations allowed) ----------------
__device__ __align__(16) uint32_t g_Mbits[DN * NWORDS]; // bit c of row j: c in nbr(j)
__device__ int   g_ncnt[DN];            // unique-neighbor count (plain rewrite each replay)
__device__ int   g_nbru[DN * KMAX];     // unique neighbor ids
__device__ float g_nbrw[DN * KMAX];     // nbrval[i, c]
__device__ int   g_rdeg[DN];            // reverse degree; zero-init, REZEROED by k_main block i
__device__ int   g_rlist[DN * RCAP];    // reverse lists, entries stored as (i+1); 0 = terminator

__device__ __forceinline__ uint32_t ld_rlx(const float* p) {
    uint32_t v;
    asm volatile("ld.relaxed.gpu.global.b32 %0, [%1];" : "=r"(v) : "l"(p) : "memory");
    return v;
}
__device__ __forceinline__ void st_rlx(float* p, float v) {
    asm volatile("st.relaxed.gpu.global.f32 [%0], %1;" :: "l"(p), "f"(v) : "memory");
}
__device__ __forceinline__ float poll_entry(const float* p) {
    uint32_t v; int it = 0;
    while ((v = ld_rlx(p)) == SENT) { if (++it > 8) __nanosleep(64); }
    return __uint_as_float(v);
}
// bits of a 32-bit word at base 'base' restricted to ids < i
__device__ __forceinline__ uint32_t mask_lt(int i, int base) {
    if (i >= base + 32) return 0xffffffffu;
    if (i <= base)      return 0u;
    return (1u << (i - base)) - 1u;
}

// ---------------- kernel 1: build + targeted sentinel fill ----------------
__global__ __launch_bounds__(256)
void k_build(const int* __restrict__ nbr,
             const float* __restrict__ dyn,
             const float* __restrict__ stat,
             float* __restrict__ out) {
    __shared__ uint32_t s_bits[8][NWORDS];
    const int lane = threadIdx.x & 31;
    const int wp   = threadIdx.x >> 5;
    const int i    = blockIdx.x * 8 + wp;

    int c = nbr[i * KMAX + lane];
    unsigned mm = __match_any_sync(0xffffffffu, c);
    bool leader = (lane == (__ffs(mm) - 1));              // first occurrence = set semantics
    unsigned kb = __ballot_sync(0xffffffffu, leader);
    int ncnt = __popc(kb);
    int slot = __popc(kb & ((1u << lane) - 1u));

    s_bits[wp][lane] = 0; s_bits[wp][lane + 32] = 0;
    __syncwarp();
    if (leader) {
        atomicOr(&s_bits[wp][c >> 5], 1u << (c & 31));
        // sentinel the polled set {(c, i) : c in nbr(i), i > c}
        if (c < i) out[(size_t)c * DN + i] = __uint_as_float(SENT);
        // tanh(z/2) = (1 - e^-z) / (1 + e^-z)
        float z = 0.7f * dyn[(size_t)i * DN + c] + 0.3f * stat[c] + 0.5f;
        float ez = __expf(-z);
        float w = __fdividef(1.f - ez, 1.f + ez);
        g_nbru[i * KMAX + slot] = c;
        g_nbrw[i * KMAX + slot] = w;
        int e = atomicAdd(&g_rdeg[c], 1);                 // zeroed by prev replay's k_main
        if (e < RCAP) g_rlist[c * RCAP + e] = i + 1;      // +1: 0 stays the terminator
    }
    if (lane == 0) g_ncnt[i] = ncnt;
    __syncwarp();
    g_Mbits[i * NWORDS + lane]      = s_bits[wp][lane];
    g_Mbits[i * NWORDS + lane + 32] = s_bits[wp][lane + 32];
}

// ---------------- kernel 2: per-COLUMN Phase-A chains (wait-free) + bulk ----------------
__global__ __launch_bounds__(NT, 16)
void k_main(const float* __restrict__ stat, float* __restrict__ out) {
    __shared__ float    s_num[DN];        // 8 KB
    __shared__ uint32_t s_cnt32[DN / 4];  // 2 KB
    __shared__ uint32_t s_Mi[NWORDS];
    __shared__ uint32_t s_skip[NWORDS];
    __shared__ int      s_nbr[KMAX];
    __shared__ float    s_w[KMAX];
    __shared__ int      s_meta[2];
    __shared__ uint8_t  s_map[DN];        // 2 KB: chain id -> slot (only chain ids ever read)
    __shared__ float    s_chainval[KMAX]; // column-chain values

    const int t = threadIdx.x;
    const int i = blockIdx.x;             // row AND column owned by this block
    const int lane = t & 31;
    const int wid  = t >> 5;

    if (t == 0) {
        s_meta[0] = g_ncnt[i];
        s_meta[1] = min(g_rdeg[i], RCAP);
        g_rdeg[i] = 0;                    // only block i reads g_rdeg[i] -> safe rezero
    }
    if (t < NWORDS) { s_Mi[t] = g_Mbits[i * NWORDS + t]; s_skip[t] = 0; }
    for (int j = t; j < DN; j += NT) s_num[j] = 0.f;
    for (int w = t; w < DN / 4; w += NT) s_cnt32[w] = 0;
    __syncthreads();
    const int ncnt = s_meta[0];
    const int rdeg = s_meta[1];
    if (t < ncnt) { s_nbr[t] = g_nbru[i * KMAX + t]; s_w[t] = g_nbrw[i * KMAX + t]; }
    __syncthreads();

    if (wid == 0) {
        // ---- Phase A: column-i chain. Entries (c, i), c in nbr(i), c < i,
        // processed ascending: every dependency (c', i) is already in s_chainval. ----
        float fb = 0.5f * stat[i];
        int pos = 0;
        for (int wi = 0; wi < NWORDS; wi++) {
            uint32_t word = s_Mi[wi] & mask_lt(i, wi * 32);
            while (word) {
                int bpos = __ffs(word) - 1; word &= word - 1;
                int c = wi * 32 + bpos;
                // parallel, wait-free loads of row c's build data (all from k_build)
                int      ncnt_c = g_ncnt[c];
                uint32_t mw0 = g_Mbits[c * NWORDS + lane];
                uint32_t mw1 = g_Mbits[c * NWORDS + 32 + lane];
                int      u   = g_nbru[c * KMAX + lane];
                float    wv  = g_nbrw[c * KMAX + lane];
                bool     vs  = lane < ncnt_c;
                uint32_t i0 = mw0 & s_Mi[lane];
                uint32_t i1 = mw1 & s_Mi[lane + 32];
                int cnt = __reduce_add_sync(0xffffffffu, __popc(i0) + __popc(i1));
                int wb = i >> 5;
                uint32_t msel = __shfl_sync(0xffffffffu, (wb < 32) ? mw0 : mw1, wb & 31);
                bool isn = (msel >> (i & 31)) & 1u;
                float val;
                if (isn) {
                    unsigned bal = __ballot_sync(0xffffffffu, vs && (u == i));
                    val = __shfl_sync(0xffffffffu, wv, __ffs(bal) - 1);
                } else if (cnt == 0) {
                    val = fb;
                } else {
                    uint32_t t0 = i0 & mask_lt(c, lane * 32);
                    uint32_t t1 = i1 & mask_lt(c, (lane + 32) * 32);
                    float num = 0.f;
                    for (;;) {
                        unsigned myc = 0xFFFFu;
                        if (t0)      myc = lane * 32 + (__ffs(t0) - 1);
                        else if (t1) myc = (lane + 32) * 32 + (__ffs(t1) - 1);
                        unsigned cp = __reduce_min_sync(0xffffffffu, myc);
                        if (cp == 0xFFFFu) break;
                        if (myc == cp) { if (t0) t0 &= t0 - 1; else t1 &= t1 - 1; }
                        unsigned bal = __ballot_sync(0xffffffffu, vs && (u == (int)cp));
                        float wc = __shfl_sync(0xffffffffu, wv, __ffs(bal) - 1);
                        num += wc * s_chainval[s_map[cp]];   // local, already computed
                    }
                    val = 0.8f * __fdividef(num, (float)cnt);
                }
                val = fminf(fmaxf(val, 0.f), 1.f);
                if (lane == 0) {
                    st_rlx(&out[(size_t)c * DN + i], val);   // publish (overwrites sentinel)
                    s_map[c] = (uint8_t)pos;
                    s_chainval[pos] = val;
                }
                __syncwarp();
                pos++;
            }
        }
    } else {
        // ---- warps 1-3: skip-set rebuild + fused count/num over reverse lists ----
        for (int e = t - 32; e < rdeg; e += 96) {
            int j = g_rlist[i * RCAP + e] - 1;
            if (j > i) atomicOr(&s_skip[j >> 5], 1u << (j & 31));
        }
        for (int s = wid - 1; s < ncnt; s += 3) {
            int c = s_nbr[s];
            bool lower = (c < i);
            float w = s_w[s];
            const int* rl = &g_rlist[c * RCAP];
            for (int e = lane; e < RCAP; e += 32) {
                int v = rl[e];
                bool act = (v != 0);
                if (!__ballot_sync(0xffffffffu, act)) break;   // terminator word
                if (act) {
                    int j = v - 1;
                    atomicAdd(&s_cnt32[j >> 2], 1u << (8 * (j & 3)));
                    if (lower && j > c)
                        atomicAdd(&s_num[j], w * poll_entry(&out[(size_t)c * DN + j]));
                }
            }
        }
    }
    __syncthreads();

    // ---- assemble + write row; Phase-A columns of row i written by OTHER blocks (skip) ----
    float* outrow = out + (size_t)i * DN;
    const float4* stat4 = reinterpret_cast<const float4*>(stat);
#pragma unroll
    for (int q = 0; q < 4; q++) {
        int w = t + q * NT;
        int j0 = 4 * w;
        uint32_t a = s_cnt32[w];
        float4 sj = stat4[w];
        float sv[4] = {sj.x, sj.y, sj.z, sj.w};
        float4 v; float* vp = &v.x;
#pragma unroll
        for (int b = 0; b < 4; b++) {
            int j = j0 + b;
            int cnt = (a >> (8 * b)) & 0xFF;
            float val = (cnt > 0) ? 0.8f * __fdividef(s_num[j], (float)cnt)
                                  : 0.5f * sv[b];
            if (j == i) val = 1.0f;
            vp[b] = fminf(fmaxf(val, 0.f), 1.f);
        }
        uint32_t skm = (s_skip[j0 >> 5] >> (j0 & 31)) & 0xFu;
        if (skm == 0) {
            reinterpret_cast<float4*>(outrow)[w] = v;
        } else {
#pragma unroll
            for (int b = 0; b < 4; b++)
                if (!((skm >> b) & 1u)) outrow[j0 + b] = vp[b];
        }
    }
    __syncthreads();
    // patch neighbor columns not owned by Phase A
    if (t < ncnt) {
        int c = s_nbr[t];
        if (!((s_skip[c >> 5] >> (c & 31)) & 1u))
            outrow[c] = fminf(fmaxf(s_w[t], 0.f), 1.f);
    }
}

// ---------------- launch ----------------
extern "C" void kernel_launch(void* const* d_in, const int* in_sizes, int n_in,
                              void* d_out, int out_size) {
    const float* dyn  = (const float*)d_in[0];   // [2048, 2048] f32
    const float* stat = (const float*)d_in[1];   // [2048] f32
    const int*   nbr  = (const int*)d_in[2];     // [2048, 32] i32
    float* out = (float*)d_out;                  // [2048, 2048] f32

    k_build<<<DN / 8, 256>>>(nbr, dyn, stat, out);
    k_main <<<DN, NT>>>(stat, out);
}

// round 16
// speedup vs baseline: 1.4179x; 1.4179x over previous
#include <cuda_runtime.h>
#include <stdint.h>

#define DN    2048
#define NWORDS  64      // 2048 bits / 32
#define KMAX    32
#define RCAP   160      // reverse-adjacency capacity (in-degree ~Poisson(31), max ~60)
#define NT     128      // k_main block size: 16 CTA/SM -> all 2048 CTAs resident
#define SENT  0xBF800000u   // bit pattern of -1.0f; legit values are in [0,1]

// ---------------- device scratch (no allocations allowed) ----------------
__device__ __align__(16) uint32_t g_Mbits[DN * NWORDS]; // bit c of row j: c in nbr(j)
__device__ int   g_ncnt[DN];            // unique-neighbor count (plain rewrite each replay)
__device__ int   g_nbru[DN * KMAX];     // unique neighbor ids
__device__ float g_nbrw[DN * KMAX];     // nbrval[i, c]
__device__ int   g_rdeg[DN];            // reverse degree; zero-init, REZEROED by k_main block i
__device__ int   g_rlist[DN * RCAP];    // reverse lists, entries stored as (i+1); 0 = terminator

__device__ __forceinline__ uint32_t ld_rlx(const float* p) {
    uint32_t v;
    asm volatile("ld.relaxed.gpu.global.b32 %0, [%1];" : "=r"(v) : "l"(p) : "memory");
    return v;
}
__device__ __forceinline__ void st_rlx(float* p, float v) {
    asm volatile("st.relaxed.gpu.global.f32 [%0], %1;" :: "l"(p), "f"(v) : "memory");
}
__device__ __forceinline__ float poll_entry(const float* p) {
    uint32_t v; int it = 0;
    while ((v = ld_rlx(p)) == SENT) { if (++it > 8) __nanosleep(64); }
    return __uint_as_float(v);
}

// ---------------- kernel 1: build + targeted sentinel fill ----------------
__global__ __launch_bounds__(256)
void k_build(const int* __restrict__ nbr,
             const float* __restrict__ dyn,
             const float* __restrict__ stat,
             float* __restrict__ out) {
    __shared__ uint32_t s_bits[8][NWORDS];
    const int lane = threadIdx.x & 31;
    const int wp   = threadIdx.x >> 5;
    const int i    = blockIdx.x * 8 + wp;

    int c = nbr[i * KMAX + lane];
    unsigned mm = __match_any_sync(0xffffffffu, c);
    bool leader = (lane == (__ffs(mm) - 1));              // first occurrence = set semantics
    unsigned kb = __ballot_sync(0xffffffffu, leader);
    int ncnt = __popc(kb);
    int slot = __popc(kb & ((1u << lane) - 1u));

    s_bits[wp][lane] = 0; s_bits[wp][lane + 32] = 0;
    __syncwarp();

    // HOISTED out of the leader branch: all lanes compute/store in parallel.
    // Duplicate-c lanes touch identical addresses with identical values — benign.
    // sentinel the polled set {(c, i) : c in nbr(i), i > c}
    if (c < i) out[(size_t)c * DN + i] = __uint_as_float(SENT);
    // tanh(z/2) = (1 - e^-z) / (1 + e^-z)  (the reference's own sigmoid identity)
    float z = 0.7f * dyn[(size_t)i * DN + c] + 0.3f * stat[c] + 0.5f;
    float ez = __expf(-z);
    float w = __fdividef(1.f - ez, 1.f + ez);

    if (leader) {
        atomicOr(&s_bits[wp][c >> 5], 1u << (c & 31));
        g_nbru[i * KMAX + slot] = c;
        g_nbrw[i * KMAX + slot] = w;
        int e = atomicAdd(&g_rdeg[c], 1);                 // zeroed by prev replay's k_main
        if (e < RCAP) g_rlist[c * RCAP + e] = i + 1;      // +1: 0 stays the terminator
    }
    if (lane == 0) g_ncnt[i] = ncnt;
    __syncwarp();
    g_Mbits[i * NWORDS + lane]      = s_bits[wp][lane];    // full-word writes: no pre-zero
    g_Mbits[i * NWORDS + lane + 32] = s_bits[wp][lane + 32];
}

// ---------------- kernel 2: sentinel chain + bulk (R14 shape) ----------------
__global__ __launch_bounds__(NT, 16)
void k_main(const float* __restrict__ stat, float* __restrict__ out) {
    __shared__ float    s_num[DN];        // 8 KB
    __shared__ uint32_t s_cnt32[DN / 4];  // 2 KB: 4 byte-counters per word (count <= 32)
    __shared__ uint32_t s_Mi[NWORDS];
    __shared__ uint32_t s_skip[NWORDS];   // columns written by Phase A
    __shared__ int      s_nbr[KMAX];
    __shared__ float    s_w[KMAX];
    __shared__ int      s_meta[2];

    const int t = threadIdx.x;
    const int i = blockIdx.x;

    if (t == 0) {
        s_meta[0] = g_ncnt[i];
        int rd = min(g_rdeg[i], RCAP);
        s_meta[1] = rd;
        g_rdeg[i] = 0;                    // only block i ever reads g_rdeg[i] -> safe rezero
    }
    if (t < NWORDS) { s_Mi[t] = g_Mbits[i * NWORDS + t]; s_skip[t] = 0; }
    for (int j = t; j < DN; j += NT) s_num[j] = 0.f;
    for (int w = t; w < DN / 4; w += NT) s_cnt32[w] = 0;
    __syncthreads();
    const int ncnt = s_meta[0];
    const int rdeg = s_meta[1];
    if (t < ncnt) { s_nbr[t] = g_nbru[i * KMAX + t]; s_w[t] = g_nbrw[i * KMAX + t]; }
    __syncthreads();

    // ---- Phase A: downstream-needed entries (i, j), i in nbr(j), j > i ----
    for (int e = 4 * (t & 31) + (t >> 5); e < rdeg; e += NT) {
        int j = g_rlist[i * RCAP + e] - 1;
        if (j <= i) continue;
        int cnt = 0; uint32_t terms = 0; float wj = 0.f;
        const uint32_t* bj = &g_Mbits[j * NWORDS];
#pragma unroll 4
        for (int s = 0; s < ncnt; s++) {
            int c = s_nbr[s];
            if (c == j) wj = s_w[s];
            if ((bj[c >> 5] >> (c & 31)) & 1u) {
                cnt++;
                if (c < i && c < j) terms |= (1u << s);
            }
        }
        bool isn = (s_Mi[j >> 5] >> (j & 31)) & 1u;
        if (isn || terms == 0) {
            // dep-free value publishes immediately (before reconvergence with pollers)
            float val = isn ? wj : (cnt > 0 ? 0.0f : 0.5f * stat[j]);
            st_rlx(&out[(size_t)i * DN + j], fminf(fmaxf(val, 0.f), 1.f));
        } else {
            float num = 0.f;
            uint32_t m = terms;
            while (m) {                         // deterministic s-ascending order
                int s = __ffs(m) - 1; m &= m - 1;
                num += s_w[s] * poll_entry(&out[(size_t)s_nbr[s] * DN + j]);
            }
            float val = 0.8f * __fdividef(num, (float)cnt);
            st_rlx(&out[(size_t)i * DN + j], fminf(fmaxf(val, 0.f), 1.f));
        }
        atomicOr(&s_skip[j >> 5], 1u << (j & 31));
    }

    // ---- fused count + num over reverse lists (terminator-scanned) ----
    {
        int wid = t >> 5, lane = t & 31;
        for (int s = wid; s < ncnt; s += NT / 32) {
            int c = s_nbr[s];
            bool lower = (c < i);
            float w = s_w[s];
            const int* rl = &g_rlist[c * RCAP];
            for (int e = lane; e < RCAP; e += 32) {
                int v = rl[e];
                bool act = (v != 0);
                if (!__ballot_sync(0xffffffffu, act)) break;   // all-zero word = end of list
                if (act) {
                    int j = v - 1;
                    atomicAdd(&s_cnt32[j >> 2], 1u << (8 * (j & 3)));
                    if (lower && j > c)
                        atomicAdd(&s_num[j], w * poll_entry(&out[(size_t)c * DN + j]));
                }
            }
        }
    }
    __syncthreads();   // also orders all Phase-A s_skip atomics before assemble

    // assemble + write row; Phase-A columns written exactly once (skipped here)
    float* outrow = out + (size_t)i * DN;
    const float4* stat4 = reinterpret_cast<const float4*>(stat);
#pragma unroll
    for (int q = 0; q < 4; q++) {
        int w = t + q * NT;
        int j0 = 4 * w;
        uint32_t a = s_cnt32[w];
        float4 sj = stat4[w];
        float sv[4] = {sj.x, sj.y, sj.z, sj.w};
        float4 v; float* vp = &v.x;
#pragma unroll
        for (int b = 0; b < 4; b++) {
            int j = j0 + b;
            int cnt = (a >> (8 * b)) & 0xFF;
            float val = (cnt > 0) ? 0.8f * __fdividef(s_num[j], (float)cnt)
                                  : 0.5f * sv[b];
            if (j == i) val = 1.0f;
            vp[b] = fminf(fmaxf(val, 0.f), 1.f);
        }
        uint32_t skm = (s_skip[j0 >> 5] >> (j0 & 31)) & 0xFu;
        if (skm == 0) {
            reinterpret_cast<float4*>(outrow)[w] = v;
        } else {
#pragma unroll
            for (int b = 0; b < 4; b++)
                if (!((skm >> b) & 1u)) outrow[j0 + b] = vp[b];
        }
    }
    __syncthreads();
    // patch neighbor columns not owned by Phase A (never read by other blocks)
    if (t < ncnt) {
        int c = s_nbr[t];
        if (!((s_skip[c >> 5] >> (c & 31)) & 1u))
            outrow[c] = fminf(fmaxf(s_w[t], 0.f), 1.f);
    }
}

// ---------------- launch ----------------
extern "C" void kernel_launch(void* const* d_in, const int* in_sizes, int n_in,
                              void* d_out, int out_size) {
    const float* dyn  = (const float*)d_in[0];   // [2048, 2048] f32
    const float* stat = (const float*)d_in[1];   // [2048] f32
    const int*   nbr  = (const int*)d_in[2];     // [2048, 32] i32
    float* out = (float*)d_out;                  // [2048, 2048] f32

    k_build<<<DN / 8, 256>>>(nbr, dyn, stat, out);
    k_main <<<DN, NT>>>(stat, out);
}

// round 17
// speedup vs baseline: 1.4525x; 1.0244x over previous
#include <cuda_runtime.h>
#include <stdint.h>

#define DN    2048
#define NWORDS  64      // 2048 bits / 32
#define KMAX    32
#define RCAP   160      // reverse-adjacency capacity (in-degree ~Poisson(31), max ~60)
#define NT     128      // k_main block size: 16 CTA/SM -> all 2048 CTAs resident
#define SENT  0xBF800000u   // bit pattern of -1.0f; legit values are in [0,1]
#define FIXS  1048576.0f    // 2^20 fixed-point scale for num
#define CNTSH 26            // count field starts at bit 26 (num < 2^25 -> no carry)

// ---------------- device scratch (no allocations allowed) ----------------
__device__ __align__(16) uint32_t g_Mbits[DN * NWORDS]; // bit c of row j: c in nbr(j)
__device__ int   g_ncnt[DN];            // unique-neighbor count (plain rewrite each replay)
__device__ int   g_nbru[DN * KMAX];     // unique neighbor ids
__device__ float g_nbrw[DN * KMAX];     // nbrval[i, c]
__device__ int   g_rdeg[DN];            // reverse degree; zero-init, REZEROED by k_main block i
__device__ int   g_rlist[DN * RCAP];    // reverse lists, entries stored as (i+1); 0 = terminator

__device__ __forceinline__ uint32_t ld_rlx(const float* p) {
    uint32_t v;
    asm volatile("ld.relaxed.gpu.global.b32 %0, [%1];" : "=r"(v) : "l"(p) : "memory");
    return v;
}
__device__ __forceinline__ void st_rlx(float* p, float v) {
    asm volatile("st.relaxed.gpu.global.f32 [%0], %1;" :: "l"(p), "f"(v) : "memory");
}
__device__ __forceinline__ float poll_entry(const float* p) {
    uint32_t v; int it = 0;
    while ((v = ld_rlx(p)) == SENT) { if (++it > 8) __nanosleep(64); }
    return __uint_as_float(v);
}

// ---------------- kernel 1: build + targeted sentinel fill ----------------
__global__ __launch_bounds__(256)
void k_build(const int* __restrict__ nbr,
             const float* __restrict__ dyn,
             const float* __restrict__ stat,
             float* __restrict__ out) {
    __shared__ uint32_t s_bits[8][NWORDS];
    const int lane = threadIdx.x & 31;
    const int wp   = threadIdx.x >> 5;
    const int i    = blockIdx.x * 8 + wp;

    int c = nbr[i * KMAX + lane];
    unsigned mm = __match_any_sync(0xffffffffu, c);
    bool leader = (lane == (__ffs(mm) - 1));              // first occurrence = set semantics
    unsigned kb = __ballot_sync(0xffffffffu, leader);
    int ncnt = __popc(kb);
    int slot = __popc(kb & ((1u << lane) - 1u));

    s_bits[wp][lane] = 0; s_bits[wp][lane + 32] = 0;
    __syncwarp();

    // HOISTED: all lanes compute/store in parallel (duplicate lanes benign).
    if (c < i) out[(size_t)c * DN + i] = __uint_as_float(SENT);
    // tanh(z/2) = (1 - e^-z) / (1 + e^-z)
    float z = 0.7f * dyn[(size_t)i * DN + c] + 0.3f * stat[c] + 0.5f;
    float ez = __expf(-z);
    float w = __fdividef(1.f - ez, 1.f + ez);

    if (leader) {
        atomicOr(&s_bits[wp][c >> 5], 1u << (c & 31));
        g_nbru[i * KMAX + slot] = c;
        g_nbrw[i * KMAX + slot] = w;
        int e = atomicAdd(&g_rdeg[c], 1);                 // zeroed by prev replay's k_main
        if (e < RCAP) g_rlist[c * RCAP + e] = i + 1;      // +1: 0 stays the terminator
    }
    if (lane == 0) g_ncnt[i] = ncnt;
    __syncwarp();
    g_Mbits[i * NWORDS + lane]      = s_bits[wp][lane];
    g_Mbits[i * NWORDS + lane + 32] = s_bits[wp][lane + 32];
}

// ---------------- kernel 2: sentinel chain + single-atomic fused count/num ----------------
__global__ __launch_bounds__(NT, 16)
void k_main(const float* __restrict__ stat, float* __restrict__ out) {
    __shared__ uint32_t s_acc[DN];        // 8 KB: count in bits[26:32), num fix20 in bits[0:26)
    __shared__ uint32_t s_Mi[NWORDS];
    __shared__ uint32_t s_skip[NWORDS];   // columns written by Phase A
    __shared__ int      s_nbr[KMAX];
    __shared__ float    s_w[KMAX];
    __shared__ float    s_rcp[KMAX + 1];  // 0.8 / (cnt * 2^20)
    __shared__ int      s_meta[2];

    const int t = threadIdx.x;
    const int i = blockIdx.x;

    if (t == 0) {
        s_meta[0] = g_ncnt[i];
        int rd = min(g_rdeg[i], RCAP);
        s_meta[1] = rd;
        g_rdeg[i] = 0;                    // only block i ever reads g_rdeg[i] -> safe rezero
    }
    if (t < NWORDS) { s_Mi[t] = g_Mbits[i * NWORDS + t]; s_skip[t] = 0; }
    if (t >= 64 && t <= 64 + KMAX)        // threads 64..96 fill the reciprocal table
        s_rcp[t - 64] = (t == 64) ? 0.f : __fdividef(0.8f, (float)(t - 64) * FIXS);
    for (int j = t; j < DN; j += NT) s_acc[j] = 0u;
    __syncthreads();
    const int ncnt = s_meta[0];
    const int rdeg = s_meta[1];
    if (t < ncnt) { s_nbr[t] = g_nbru[i * KMAX + t]; s_w[t] = g_nbrw[i * KMAX + t]; }
    __syncthreads();

    // ---- Phase A: downstream-needed entries (i, j), i in nbr(j), j > i ----
    for (int e = 4 * (t & 31) + (t >> 5); e < rdeg; e += NT) {
        int j = g_rlist[i * RCAP + e] - 1;
        if (j <= i) continue;
        int cnt = 0; uint32_t terms = 0; float wj = 0.f;
        const uint32_t* bj = &g_Mbits[j * NWORDS];
#pragma unroll 4
        for (int s = 0; s < ncnt; s++) {
            int c = s_nbr[s];
            if (c == j) wj = s_w[s];
            if ((bj[c >> 5] >> (c & 31)) & 1u) {
                cnt++;
                if (c < i && c < j) terms |= (1u << s);
            }
        }
        bool isn = (s_Mi[j >> 5] >> (j & 31)) & 1u;
        if (isn || terms == 0) {
            // dep-free value publishes immediately (before reconvergence with pollers)
            float val = isn ? wj : (cnt > 0 ? 0.0f : 0.5f * stat[j]);
            st_rlx(&out[(size_t)i * DN + j], fminf(fmaxf(val, 0.f), 1.f));
        } else {
            float num = 0.f;
            uint32_t m = terms;
            while (m) {                         // deterministic s-ascending order
                int s = __ffs(m) - 1; m &= m - 1;
                num += s_w[s] * poll_entry(&out[(size_t)s_nbr[s] * DN + j]);
            }
            float val = 0.8f * __fdividef(num, (float)cnt);
            st_rlx(&out[(size_t)i * DN + j], fminf(fmaxf(val, 0.f), 1.f));
        }
        atomicOr(&s_skip[j >> 5], 1u << (j & 31));
    }

    // ---- fused count+num: ONE shared atomic per (c, j) pair ----
    //   inc = (1 << 26)                      [count]
    //       + round(w_c * out[c][j] * 2^20)  [num, only if c < i && j > c]
    // integer accumulation: exact, order-independent, no carry across fields.
    {
        int wid = t >> 5, lane = t & 31;
        for (int s = wid; s < ncnt; s += NT / 32) {
            int c = s_nbr[s];
            bool lower = (c < i);
            float w = s_w[s];
            const int* rl = &g_rlist[c * RCAP];
            for (int e = lane; e < RCAP; e += 32) {
                int v = rl[e];
                bool act = (v != 0);
                if (!__ballot_sync(0xffffffffu, act)) break;   // all-zero word = end of list
                if (act) {
                    int j = v - 1;
                    uint32_t inc = 1u << CNTSH;
                    if (lower && j > c)
                        inc += __float2uint_rn(w * poll_entry(&out[(size_t)c * DN + j]) * FIXS);
                    atomicAdd(&s_acc[j], inc);
                }
            }
        }
    }
    __syncthreads();   // also orders all Phase-A s_skip atomics before assemble

    // assemble + write row; Phase-A columns written exactly once (skipped here)
    float* outrow = out + (size_t)i * DN;
    const float4* stat4 = reinterpret_cast<const float4*>(stat);
    const uint4*  acc4  = reinterpret_cast<const uint4*>(s_acc);
#pragma unroll
    for (int q = 0; q < 4; q++) {
        int w = t + q * NT;
        int j0 = 4 * w;
        uint4 aa = acc4[w];
        uint32_t av[4] = {aa.x, aa.y, aa.z, aa.w};
        float4 sj = stat4[w];
        float sv[4] = {sj.x, sj.y, sj.z, sj.w};
        float4 v; float* vp = &v.x;
#pragma unroll
        for (int b = 0; b < 4; b++) {
            int j = j0 + b;
            uint32_t a = av[b];
            int cnt = a >> CNTSH;
            float val = (cnt > 0) ? (float)(a & ((1u << CNTSH) - 1u)) * s_rcp[cnt]
                                  : 0.5f * sv[b];
            if (j == i) val = 1.0f;
            vp[b] = fminf(fmaxf(val, 0.f), 1.f);
        }
        uint32_t skm = (s_skip[j0 >> 5] >> (j0 & 31)) & 0xFu;
        if (skm == 0) {
            reinterpret_cast<float4*>(outrow)[w] = v;
        } else {
#pragma unroll
            for (int b = 0; b < 4; b++)
                if (!((skm >> b) & 1u)) outrow[j0 + b] = vp[b];
        }
    }
    __syncthreads();
    // patch neighbor columns not owned by Phase A (never read by other blocks)
    if (t < ncnt) {
        int c = s_nbr[t];
        if (!((s_skip[c >> 5] >> (c & 31)) & 1u))
            outrow[c] = fminf(fmaxf(s_w[t], 0.f), 1.f);
    }
}

// ---------------- launch ----------------
extern "C" void kernel_launch(void* const* d_in, const int* in_sizes, int n_in,
                              void* d_out, int out_size) {
    const float* dyn  = (const float*)d_in[0];   // [2048, 2048] f32
    const float* stat = (const float*)d_in[1];   // [2048] f32
    const int*   nbr  = (const int*)d_in[2];     // [2048, 32] i32
    float* out = (float*)d_out;                  // [2048, 2048] f32

    k_build<<<DN / 8, 256>>>(nbr, dyn, stat, out);
    k_main <<<DN, NT>>>(stat, out);
}